// round 2
// baseline (speedup 1.0000x reference)
#include <cuda_runtime.h>
#include <math.h>

// Scratch for E = exp(x @ W^T), 256x512 fp32 (allocation-free per harness rules)
__device__ float g_E[256 * 512];

constexpr int BM = 32, BN = 32, BK = 32;

// GEMM1 (NT): E[m,n] = expf( sum_k X[m,k] * W[n,k] )
// M=256, N=512, K=1024. X row-major (K contig), W row-major (K contig).
__global__ __launch_bounds__(256) void gemm1_exp_kernel(
    const float* __restrict__ X, const float* __restrict__ W)
{
    __shared__ float As[BM][BK + 1];
    __shared__ float Bs[BN][BK + 1];

    const int tid = threadIdx.x;
    const int m0 = blockIdx.y * BM;
    const int n0 = blockIdx.x * BN;

    // compute mapping: 16x16 thread grid, each thread a 2x2 micro-tile
    const int tr = tid >> 4;      // 0..15
    const int tc = tid & 15;      // 0..15
    // load mapping: 32 rows, 8 float4 per row
    const int lr = tid >> 3;            // 0..31
    const int lc = (tid & 7) << 2;      // 0,4,...,28

    float acc00 = 0.f, acc01 = 0.f, acc10 = 0.f, acc11 = 0.f;

    for (int k0 = 0; k0 < 1024; k0 += BK) {
        float4 a = *(const float4*)(X + (m0 + lr) * 1024 + k0 + lc);
        As[lr][lc + 0] = a.x; As[lr][lc + 1] = a.y;
        As[lr][lc + 2] = a.z; As[lr][lc + 3] = a.w;
        float4 b = *(const float4*)(W + (n0 + lr) * 1024 + k0 + lc);
        Bs[lr][lc + 0] = b.x; Bs[lr][lc + 1] = b.y;
        Bs[lr][lc + 2] = b.z; Bs[lr][lc + 3] = b.w;
        __syncthreads();

        #pragma unroll
        for (int k = 0; k < BK; k++) {
            float a0 = As[2 * tr][k];
            float a1 = As[2 * tr + 1][k];
            float b0 = Bs[2 * tc][k];
            float b1 = Bs[2 * tc + 1][k];
            acc00 += a0 * b0; acc01 += a0 * b1;
            acc10 += a1 * b0; acc11 += a1 * b1;
        }
        __syncthreads();
    }

    const int m = m0 + 2 * tr;
    const int n = n0 + 2 * tc;
    g_E[m * 512 + n]           = expf(acc00);
    g_E[m * 512 + n + 1]       = expf(acc01);
    g_E[(m + 1) * 512 + n]     = expf(acc10);
    g_E[(m + 1) * 512 + n + 1] = expf(acc11);
}

// GEMM2 (NN): Y[m,n] = sum_k E[m,k] * expf(U[k,n]) + 512
// M=256, N=1024, K=512. E row-major (K contig), U row-major (N contig).
__global__ __launch_bounds__(256) void gemm2_kernel(
    const float* __restrict__ U, float* __restrict__ Y)
{
    __shared__ float As[BM][BK + 1];   // E tile, (m, k)
    __shared__ float Bs[BK][BN];       // exp(U) tile, (k, n)

    const int tid = threadIdx.x;
    const int m0 = blockIdx.y * BM;
    const int n0 = blockIdx.x * BN;

    const int tr = tid >> 4;
    const int tc = tid & 15;
    const int lr = tid >> 3;
    const int lc = (tid & 7) << 2;

    float acc00 = 0.f, acc01 = 0.f, acc10 = 0.f, acc11 = 0.f;

    for (int k0 = 0; k0 < 512; k0 += BK) {
        float4 a = *(const float4*)(g_E + (m0 + lr) * 512 + k0 + lc);
        As[lr][lc + 0] = a.x; As[lr][lc + 1] = a.y;
        As[lr][lc + 2] = a.z; As[lr][lc + 3] = a.w;

        float4 b = *(const float4*)(U + (k0 + lr) * 1024 + n0 + lc);
        float4 be;
        be.x = expf(b.x); be.y = expf(b.y);
        be.z = expf(b.z); be.w = expf(b.w);
        *(float4*)&Bs[lr][lc] = be;
        __syncthreads();

        #pragma unroll
        for (int k = 0; k < BK; k++) {
            float a0 = As[2 * tr][k];
            float a1 = As[2 * tr + 1][k];
            float b0 = Bs[k][2 * tc];
            float b1 = Bs[k][2 * tc + 1];
            acc00 += a0 * b0; acc01 += a0 * b1;
            acc10 += a1 * b0; acc11 += a1 * b1;
        }
        __syncthreads();
    }

    const int m = m0 + 2 * tr;
    const int n = n0 + 2 * tc;
    Y[m * 1024 + n]           = acc00 + 512.0f;
    Y[m * 1024 + n + 1]       = acc01 + 512.0f;
    Y[(m + 1) * 1024 + n]     = acc10 + 512.0f;
    Y[(m + 1) * 1024 + n + 1] = acc11 + 512.0f;
}

extern "C" void kernel_launch(void* const* d_in, const int* in_sizes, int n_in,
                              void* d_out, int out_size)
{
    const float* x = (const float*)d_in[0];   // 256 x 1024
    const float* W = (const float*)d_in[1];   // 512 x 1024
    const float* u = (const float*)d_in[2];   // 512 x 1024
    float* y = (float*)d_out;                 // 256 x 1024

    // GEMM1: E = exp(x @ W^T), grid: N-tiles x M-tiles = 16 x 8 = 128 blocks
    gemm1_exp_kernel<<<dim3(512 / BN, 256 / BM), 256>>>(x, W);
    // GEMM2: y = E @ exp(u) + 512, grid: 32 x 8 = 256 blocks
    gemm2_kernel<<<dim3(1024 / BN, 256 / BM), 256>>>(u, y);
}

// round 4
// speedup vs baseline: 2.2469x; 2.2469x over previous
#include <cuda_runtime.h>
#include <cuda_bf16.h>
#include <cstdint>
#include <math.h>

// ---------------- device scratch (allocation-free) ----------------
__device__ __align__(16) __nv_bfloat16 g_xhi[256 * 1024];
__device__ __align__(16) __nv_bfloat16 g_xlo[256 * 1024];
__device__ __align__(16) __nv_bfloat16 g_Whi[512 * 1024];
__device__ __align__(16) __nv_bfloat16 g_Wlo[512 * 1024];
__device__ __align__(16) __nv_bfloat16 g_uT [1024 * 512];   // uT[n][k] = bf16(expm1(u[k][n]))
__device__ __align__(16) __nv_bfloat16 g_Ebf[256 * 512];    // bf16(E)
__device__ float g_rs[16 * 256];                            // per-(ntile,row) fp32 rowsums of E

// ---------------- helpers ----------------
__device__ __forceinline__ uint32_t smem_u32(const void* p) {
    uint32_t a;
    asm("{ .reg .u64 t; cvta.to.shared.u64 t, %1; cvt.u32.u64 %0, t; }" : "=r"(a) : "l"(p));
    return a;
}
__device__ __forceinline__ void cp16(uint32_t dst, const void* src) {
    asm volatile("cp.async.cg.shared.global [%0], [%1], 16;" :: "r"(dst), "l"(src) : "memory");
}
#define CP_COMMIT() asm volatile("cp.async.commit_group;" ::: "memory")
#define CP_WAIT1()  asm volatile("cp.async.wait_group 1;" ::: "memory")
#define CP_WAIT0()  asm volatile("cp.async.wait_group 0;" ::: "memory")

__device__ __forceinline__ void ldsm4(uint32_t* r, uint32_t addr) {
    asm volatile("ldmatrix.sync.aligned.m8n8.x4.shared.b16 {%0,%1,%2,%3}, [%4];"
        : "=r"(r[0]), "=r"(r[1]), "=r"(r[2]), "=r"(r[3]) : "r"(addr));
}
__device__ __forceinline__ void mma_bf16(float* c, const uint32_t* a, uint32_t b0, uint32_t b1) {
    asm volatile("mma.sync.aligned.m16n8k16.row.col.f32.bf16.bf16.f32 "
        "{%0,%1,%2,%3}, {%4,%5,%6,%7}, {%8,%9}, {%0,%1,%2,%3};"
        : "+f"(c[0]), "+f"(c[1]), "+f"(c[2]), "+f"(c[3])
        : "r"(a[0]), "r"(a[1]), "r"(a[2]), "r"(a[3]), "r"(b0), "r"(b1));
}

__device__ __forceinline__ void split4(float4 v, uint2& hi, uint2& lo) {
    __nv_bfloat16 h0 = __float2bfloat16(v.x), h1 = __float2bfloat16(v.y);
    __nv_bfloat16 h2 = __float2bfloat16(v.z), h3 = __float2bfloat16(v.w);
    __nv_bfloat162 hp0{h0, h1}, hp1{h2, h3};
    __nv_bfloat162 lp0{__float2bfloat16(v.x - __bfloat162float(h0)),
                       __float2bfloat16(v.y - __bfloat162float(h1))};
    __nv_bfloat162 lp1{__float2bfloat16(v.z - __bfloat162float(h2)),
                       __float2bfloat16(v.w - __bfloat162float(h3))};
    hi = make_uint2(*(uint32_t*)&hp0, *(uint32_t*)&hp1);
    lo = make_uint2(*(uint32_t*)&lp0, *(uint32_t*)&lp1);
}

// ============================================================
// Prep: bf16 hi/lo splits of x and W; uT[n][k] = bf16(expm1(u[k][n]))
// blocks [0,256): x   [256,768): W   [768,1280): u transpose tiles
// ============================================================
__global__ __launch_bounds__(256) void prep_kernel(
    const float* __restrict__ x, const float* __restrict__ W, const float* __restrict__ u)
{
    __shared__ __nv_bfloat16 tt[32][33];
    const int b = blockIdx.x, t = threadIdx.x;
    if (b < 256) {
        int idx = b * 256 + t;                // float4 index into x
        float4 v = ((const float4*)x)[idx];
        uint2 hi, lo; split4(v, hi, lo);
        *(uint2*)&g_xhi[idx * 4] = hi;
        *(uint2*)&g_xlo[idx * 4] = lo;
    } else if (b < 768) {
        int idx = (b - 256) * 256 + t;        // float4 index into W
        float4 v = ((const float4*)W)[idx];
        uint2 hi, lo; split4(v, hi, lo);
        *(uint2*)&g_Whi[idx * 4] = hi;
        *(uint2*)&g_Wlo[idx * 4] = lo;
    } else {
        int id = b - 768;                     // 32 x 16 tiles of 32x32
        int n0 = (id & 31) * 32, k0 = (id >> 5) * 32;
        int i = t >> 5, j = t & 31;
        #pragma unroll
        for (int r = 0; r < 4; r++) {
            int ki = i + r * 8;
            tt[ki][j] = __float2bfloat16(expm1f(u[(k0 + ki) * 1024 + n0 + j]));
        }
        __syncthreads();
        #pragma unroll
        for (int r = 0; r < 4; r++) {
            int ni = i + r * 8;
            g_uT[(n0 + ni) * 512 + k0 + j] = tt[j][ni];
        }
    }
}

// ============================================================
// GEMM1: E = exp(x @ W^T), bf16x3, mma.sync
// tile 32(M) x 32(N), K=1024 in 16 chunks of 64; 128 thr (4 warps 2x2 of 16x16)
// ============================================================
constexpr int G1_TILE_B  = 32 * 72 * 2;      // 4608 B (padded rows: 72 bf16)
constexpr int G1_STAGE_B = 4 * G1_TILE_B;    // Ahi|Alo|Bhi|Blo

__global__ __launch_bounds__(128) void gemm1_kernel()
{
    __shared__ __align__(16) __nv_bfloat16 sm[2 * 4 * 32 * 72];
    __shared__ float srs[2][32];
    const int tid = threadIdx.x, lane = tid & 31, wid = tid >> 5;
    const int nt = blockIdx.x;
    const int m0 = blockIdx.y * 32, n0 = nt * 32;
    const uint32_t sb = smem_u32(sm);

    const __nv_bfloat16* base0 = g_xhi + m0 * 1024;
    const __nv_bfloat16* base1 = g_xlo + m0 * 1024;
    const __nv_bfloat16* base2 = g_Whi + n0 * 1024;
    const __nv_bfloat16* base3 = g_Wlo + n0 * 1024;

    const int wm = wid >> 1, wn = wid & 1;
    const int lrow = lane & 15;
    const int lk   = (lane >> 4) << 3;       // 0 or 8
    const uint32_t aRow = (uint32_t)(((wm * 16 + lrow) * 72 + lk) * 2);
    const uint32_t bRow = (uint32_t)(((wn * 16 + lrow) * 72 + lk) * 2);

    float acc0[4] = {0.f, 0.f, 0.f, 0.f};
    float acc1[4] = {0.f, 0.f, 0.f, 0.f};

    const int c8 = tid & 7;                   // 16B segment within row
    const int r8 = tid >> 3;                  // 0..15

    #define G1_ISSUE(c) do { \
        const int k0 = (c) * 64; \
        const uint32_t d0 = sb + ((c) & 1) * G1_STAGE_B; \
        _Pragma("unroll") \
        for (int ii = 0; ii < 8; ii++) { \
            const int tile = ii >> 1; \
            const int r = ((ii & 1) << 4) + r8; \
            const __nv_bfloat16* src = \
                (tile == 0 ? base0 : tile == 1 ? base1 : tile == 2 ? base2 : base3) \
                + r * 1024 + k0 + c8 * 8; \
            cp16(d0 + tile * G1_TILE_B + (uint32_t)((r * 72 + c8 * 8) * 2), src); \
        } \
        CP_COMMIT(); \
    } while (0)

    G1_ISSUE(0);
    G1_ISSUE(1);

    for (int c = 0; c < 16; c++) {
        if (c == 15) { CP_WAIT0(); } else { CP_WAIT1(); }
        __syncthreads();
        const uint32_t st = sb + (c & 1) * G1_STAGE_B;
        #pragma unroll
        for (int p = 0; p < 3; p++) {
            const uint32_t aOff = st + (p == 2 ? G1_TILE_B : 0) + aRow;
            const uint32_t bOff = st + 2 * G1_TILE_B + (p == 1 ? G1_TILE_B : 0) + bRow;
            #pragma unroll
            for (int ks = 0; ks < 4; ks++) {
                uint32_t a[4], bfr[4];
                ldsm4(a,   aOff + ks * 32);
                ldsm4(bfr, bOff + ks * 32);
                mma_bf16(acc0, a, bfr[0], bfr[2]);
                mma_bf16(acc1, a, bfr[1], bfr[3]);
            }
        }
        __syncthreads();
        if (c + 2 < 16) G1_ISSUE(c + 2);
    }
    #undef G1_ISSUE

    // ---------- epilogue: exp, bf16 E, fp32 rowsum ----------
    const int qr = lane >> 2;              // 0..7
    const int qc = (lane & 3) * 2;
    const int mrow0 = m0 + wm * 16 + qr;
    const int mrow1 = mrow0 + 8;
    float p0 = 0.f, p1 = 0.f;
    #pragma unroll
    for (int g = 0; g < 2; g++) {
        float* acc = g ? acc1 : acc0;
        float e0 = expf(acc[0]), e1 = expf(acc[1]);
        float e2 = expf(acc[2]), e3 = expf(acc[3]);
        p0 += e0 + e1; p1 += e2 + e3;
        const int n = n0 + wn * 16 + g * 8 + qc;
        __nv_bfloat162 v0 = __floats2bfloat162_rn(e0, e1);
        __nv_bfloat162 v1 = __floats2bfloat162_rn(e2, e3);
        *(uint32_t*)&g_Ebf[mrow0 * 512 + n] = *(uint32_t*)&v0;
        *(uint32_t*)&g_Ebf[mrow1 * 512 + n] = *(uint32_t*)&v1;
    }
    p0 += __shfl_xor_sync(0xFFFFFFFFu, p0, 1);
    p0 += __shfl_xor_sync(0xFFFFFFFFu, p0, 2);
    p1 += __shfl_xor_sync(0xFFFFFFFFu, p1, 1);
    p1 += __shfl_xor_sync(0xFFFFFFFFu, p1, 2);
    if ((lane & 3) == 0) {
        srs[wn][wm * 16 + qr]     = p0;
        srs[wn][wm * 16 + qr + 8] = p1;
    }
    __syncthreads();
    if (tid < 32) g_rs[nt * 256 + m0 + tid] = srs[0][tid] + srs[1][tid];
}

// ============================================================
// GEMM2: y = E_bf16 @ uT^T + rowsum(E) + 512
// tile 32(M) x 64(N), K=512 in 8 chunks of 64; 128 thr (warp tile 16x32)
// ============================================================
constexpr int G2_A_B     = 32 * 72 * 2;           // 4608
constexpr int G2_B_B     = 64 * 72 * 2;           // 9216
constexpr int G2_STAGE_B = G2_A_B + G2_B_B;       // 13824

__global__ __launch_bounds__(128) void gemm2_kernel(float* __restrict__ Y)
{
    __shared__ __align__(16) __nv_bfloat16 sm[2 * (32 * 72 + 64 * 72)];
    __shared__ float rst[32];
    const int tid = threadIdx.x, lane = tid & 31, wid = tid >> 5;
    const int m0 = blockIdx.y * 32, n0 = blockIdx.x * 64;
    const uint32_t sb = smem_u32(sm);

    if (tid < 32) {
        float s = 512.0f;
        #pragma unroll
        for (int j = 0; j < 16; j++) s += g_rs[j * 256 + m0 + tid];
        rst[tid] = s;
    }

    const int wm = wid >> 1, wn = wid & 1;
    const int lrow = lane & 15;
    const int lk   = (lane >> 4) << 3;
    const uint32_t aRow  = (uint32_t)(((wm * 16 + lrow) * 72 + lk) * 2);
    const uint32_t b0Row = (uint32_t)(((wn * 32 + lrow) * 72 + lk) * 2);
    const uint32_t b1Row = b0Row + 16 * 72 * 2;

    float acc[4][4] = {};

    const int c8 = tid & 7;
    const int r8 = tid >> 3;

    #define G2_ISSUE(c) do { \
        const int k0 = (c) * 64; \
        const uint32_t d0 = sb + ((c) & 1) * G2_STAGE_B; \
        _Pragma("unroll") \
        for (int ii = 0; ii < 6; ii++) { \
            if (ii < 2) { \
                const int r = ii * 16 + r8; \
                cp16(d0 + (uint32_t)((r * 72 + c8 * 8) * 2), \
                     g_Ebf + (m0 + r) * 512 + k0 + c8 * 8); \
            } else { \
                const int r = (ii - 2) * 16 + r8; \
                cp16(d0 + G2_A_B + (uint32_t)((r * 72 + c8 * 8) * 2), \
                     g_uT + (n0 + r) * 512 + k0 + c8 * 8); \
            } \
        } \
        CP_COMMIT(); \
    } while (0)

    G2_ISSUE(0);
    G2_ISSUE(1);

    for (int c = 0; c < 8; c++) {
        if (c == 7) { CP_WAIT0(); } else { CP_WAIT1(); }
        __syncthreads();
        const uint32_t st = sb + (c & 1) * G2_STAGE_B;
        #pragma unroll
        for (int ks = 0; ks < 4; ks++) {
            uint32_t a[4], b0f[4], b1f[4];
            ldsm4(a,   st + aRow + ks * 32);
            ldsm4(b0f, st + G2_A_B + b0Row + ks * 32);
            ldsm4(b1f, st + G2_A_B + b1Row + ks * 32);
            mma_bf16(acc[0], a, b0f[0], b0f[2]);
            mma_bf16(acc[1], a, b0f[1], b0f[3]);
            mma_bf16(acc[2], a, b1f[0], b1f[2]);
            mma_bf16(acc[3], a, b1f[1], b1f[3]);
        }
        __syncthreads();
        if (c + 2 < 8) G2_ISSUE(c + 2);
    }
    #undef G2_ISSUE

    // ---------- epilogue ----------
    const int qr = lane >> 2;
    const int qc = (lane & 3) * 2;
    const int mrow0 = m0 + wm * 16 + qr;
    const int mrow1 = mrow0 + 8;
    const float r0v = rst[wm * 16 + qr];
    const float r1v = rst[wm * 16 + qr + 8];
    #pragma unroll
    for (int g = 0; g < 4; g++) {
        const int n = n0 + wn * 32 + g * 8 + qc;
        *(float2*)(Y + mrow0 * 1024 + n) = make_float2(acc[g][0] + r0v, acc[g][1] + r0v);
        *(float2*)(Y + mrow1 * 1024 + n) = make_float2(acc[g][2] + r1v, acc[g][3] + r1v);
    }
}

// ============================================================
extern "C" void kernel_launch(void* const* d_in, const int* in_sizes, int n_in,
                              void* d_out, int out_size)
{
    const float* x = (const float*)d_in[0];   // 256 x 1024
    const float* W = (const float*)d_in[1];   // 512 x 1024
    const float* u = (const float*)d_in[2];   // 512 x 1024
    float* y = (float*)d_out;                 // 256 x 1024

    prep_kernel<<<1280, 256>>>(x, W, u);
    gemm1_kernel<<<dim3(16, 8), 128>>>();
    gemm2_kernel<<<dim3(16, 8), 128>>>(y);
}